// round 13
// baseline (speedup 1.0000x reference)
#include <cuda_runtime.h>
#include <cuda_fp16.h>
#include <cstdint>
#include <cstddef>

#define NB    16
#define CC    192
#define HH    56
#define WW    56
#define HWP   (HH*WW)          // 3136
#define NPIX  (NB*HWP)         // 50176
#define HEADS 6
#define CHN   32
#define KT    486              // 81 * 6
#define KTP   648              // padded: 54 groups * 12
#define SCALE 0.17677669529663689f   // 32^-0.5

// ---------------- scratch (device globals; no runtime allocation) -------------
__device__ float  g_v   [NB*CC*HWP];                 // value projection    (38.5 MB)
// att layout: [n][head][kout][pixel][12] in FP16 (65 MB, plane-major)
__device__ __half g_att [(size_t)NB*HEADS*9*HWP*12];
__device__ float  g_wpad[CC*KTP];                    // padded Wa           (497 KB)

// ---------------- packed f32x2 helpers ---------------------------------------
#define FMA2(acc,a,b) asm("fma.rn.f32x2 %0, %1, %2, %0;" : "+l"(acc) : "l"(a), "l"(b))

__device__ __forceinline__ unsigned long long pack2(float x, float y) {
    unsigned long long r;
    asm("mov.b64 %0, {%1, %2};" : "=l"(r) : "r"(__float_as_uint(x)), "r"(__float_as_uint(y)));
    return r;
}
__device__ __forceinline__ void unpack2(unsigned long long v, float& x, float& y) {
    unsigned int lo, hi;
    asm("mov.b64 {%0, %1}, %2;" : "=r"(lo), "=r"(hi) : "l"(v));
    x = __uint_as_float(lo); y = __uint_as_float(hi);
}

// ============================================================================
// Wa pre-pad: [192][486] -> [192][648], group g's 9 cols at 12g..12g+8, pad 0.
// ============================================================================
__global__ void pad_wa_kernel(const float* __restrict__ Wa, float* __restrict__ Wp)
{
    int i = blockIdx.x * 256 + threadIdx.x;
    if (i >= CC*KTP) return;
    int c = i / KTP, col = i - c*KTP;
    int g = col / 12, u = col - g*12;
    Wp[i] = (u < 9) ? Wa[c*KT + g*9 + u] : 0.0f;
}

// ============================================================================
// Kernel A: 192x192 pointwise GEMM (value projection). Exact R8 version.
// ============================================================================
__global__ void __launch_bounds__(192, 3) gemm192_kernel(
    const float* __restrict__ X, const float* __restrict__ Wm,
    const float* __restrict__ bias, float* __restrict__ Out)
{
    __shared__ float xs[48][128];
    __shared__ float ws[48][96];
    const int tid  = threadIdx.x;
    const int b    = blockIdx.x;
    const int pt   = b >> 1;
    const int dt   = b & 1;
    const int g0   = pt * 128;
    const int dbase= dt * 96;
    const int warp = tid >> 5, lane = tid & 31;
    const int wd   = warp % 3, wp = warp / 3;
    const int ld   = lane >> 3, lp = lane & 7;
    const int d0   = wd*32 + ld*8;
    const int p0   = wp*64 + lp*8;

    unsigned long long acc[8][4];
    #pragma unroll
    for (int di = 0; di < 8; di++) {
        float bb = bias ? bias[dbase + d0 + di] : 0.0f;
        unsigned long long b2 = pack2(bb, bb);
        #pragma unroll
        for (int pp = 0; pp < 4; pp++) acc[di][pp] = b2;
    }

    for (int kc = 0; kc < 4; kc++) {
        __syncthreads();
        #pragma unroll
        for (int s = 0; s < 8; s++) {
            int idx = tid + s*192;
            int k = idx >> 5, p4 = idx & 31;
            int g = g0 + p4*4;
            int n = g / HWP, hw = g - n*HWP;
            *(float4*)&xs[k][p4*4] =
                *(const float4*)&X[((size_t)(n*CC) + kc*48 + k)*HWP + hw];
        }
        #pragma unroll
        for (int s = 0; s < 6; s++) {
            int idx = tid + s*192;
            int k = idx / 24, c4 = idx - k*24;
            *(float4*)&ws[k][c4*4] =
                *(const float4*)&Wm[(size_t)(kc*48 + k)*192 + dbase + c4*4];
        }
        __syncthreads();

        #pragma unroll 4
        for (int r = 0; r < 48; r++) {
            float4 wa = *(const float4*)&ws[r][d0];
            float4 wb = *(const float4*)&ws[r][d0+4];
            ulonglong2 xv0 = *(const ulonglong2*)&xs[r][p0];
            ulonglong2 xv1 = *(const ulonglong2*)&xs[r][p0+4];
            unsigned long long xp[4] = {xv0.x, xv0.y, xv1.x, xv1.y};
            unsigned long long w2[8];
            w2[0]=pack2(wa.x,wa.x); w2[1]=pack2(wa.y,wa.y);
            w2[2]=pack2(wa.z,wa.z); w2[3]=pack2(wa.w,wa.w);
            w2[4]=pack2(wb.x,wb.x); w2[5]=pack2(wb.y,wb.y);
            w2[6]=pack2(wb.z,wb.z); w2[7]=pack2(wb.w,wb.w);
            #pragma unroll
            for (int di = 0; di < 8; di++)
                #pragma unroll
                for (int pp = 0; pp < 4; pp++)
                    FMA2(acc[di][pp], xp[pp], w2[di]);
        }
    }

    #pragma unroll
    for (int s = 0; s < 2; s++) {
        int g = g0 + p0 + s*4;
        int n = g / HWP, hw = g - n*HWP;
        #pragma unroll
        for (int di = 0; di < 8; di++) {
            ulonglong2 uv; uv.x = acc[di][2*s]; uv.y = acc[di][2*s+1];
            *(ulonglong2*)&Out[((size_t)(n*CC) + dbase + d0 + di)*HWP + hw] = uv;
        }
    }
}

// ============================================================================
// Kernel B: attention logits GEMM + fused register softmax. Exact R8 version
// (fp32 weights in smem, in-loop packing; FP16 plane-major output).
// ============================================================================
#define ATT_SMEM_BYTES ((32*64 + 32*KTP)*4)      // 91136

__global__ void __launch_bounds__(864, 1) att_kernel(
    const float* __restrict__ X, const float* __restrict__ Wpad,
    const float* __restrict__ ba, __half* __restrict__ Att)
{
    extern __shared__ float sm[];
    float* xs = sm;                 // [32][64]
    float* ws = sm + 32*64;         // [32][648]
    const int tid = threadIdx.x;
    const int cg  = tid >> 4;       // 0..53  (= head*9 + kout)
    const int pg  = tid & 15;       // 0..15 -> px [4pg, 4pg+4)
    const int bb  = blockIdx.x;
    const int n   = bb / 49;
    const int hw0 = (bb - n*49) * 64;

    unsigned long long acc[9][2];
    #pragma unroll
    for (int u = 0; u < 9; u++) {
        float bv = ba[9*cg + u];
        unsigned long long b2 = pack2(bv, bv);
        acc[u][0] = b2; acc[u][1] = b2;
    }

    for (int kc = 0; kc < 6; kc++) {
        __syncthreads();
        if (tid < 512) {
            int k = tid >> 4, p4 = tid & 15;
            *(float4*)&xs[k*64 + p4*4] =
                *(const float4*)&X[((size_t)(n*CC) + kc*32 + k)*HWP + hw0 + p4*4];
        }
        #pragma unroll
        for (int s = 0; s < 6; s++) {
            int idx = tid + s*864;
            int k = idx / 162, c4 = idx - k*162;
            *(float4*)&ws[k*KTP + c4*4] =
                *(const float4*)&Wpad[(size_t)(kc*32 + k)*KTP + c4*4];
        }
        __syncthreads();

        #pragma unroll 2
        for (int r = 0; r < 32; r++) {
            float4 q0 = *(const float4*)&ws[r*KTP + 12*cg];
            float4 q1 = *(const float4*)&ws[r*KTP + 12*cg + 4];
            float  q8 = ws[r*KTP + 12*cg + 8];
            ulonglong2 xv = *(const ulonglong2*)&xs[r*64 + 4*pg];
            unsigned long long xp0 = xv.x, xp1 = xv.y;
            float wv[9] = {q0.x,q0.y,q0.z,q0.w,q1.x,q1.y,q1.z,q1.w,q8};
            #pragma unroll
            for (int u = 0; u < 9; u++) {
                unsigned long long w2 = pack2(wv[u], wv[u]);
                FMA2(acc[u][0], xp0, w2);
                FMA2(acc[u][1], xp1, w2);
            }
        }
    }

    __half* planeBase = Att + ((size_t)n*54 + cg)*HWP*12;

    #pragma unroll
    for (int pp = 0; pp < 2; pp++) {
        float z0[9], z1[9];
        #pragma unroll
        for (int u = 0; u < 9; u++) unpack2(acc[u][pp], z0[u], z1[u]);
        #pragma unroll
        for (int half = 0; half < 2; half++) {
            float* z = half ? z1 : z0;
            float m = z[0];
            #pragma unroll
            for (int u = 1; u < 9; u++) m = fmaxf(m, z[u]);
            float e[9], s = 0.0f;
            #pragma unroll
            for (int u = 0; u < 9; u++) { e[u] = __expf((z[u]-m)*SCALE); s += e[u]; }
            float inv = 1.0f / s;
            int px = 4*pg + 2*pp + half;
            __half* dst = planeBase + (size_t)(hw0 + px)*12;
            __half2 h01 = __floats2half2_rn(e[0]*inv, e[1]*inv);
            __half2 h23 = __floats2half2_rn(e[2]*inv, e[3]*inv);
            __half2 h45 = __floats2half2_rn(e[4]*inv, e[5]*inv);
            __half2 h67 = __floats2half2_rn(e[6]*inv, e[7]*inv);
            __half2 h8x = __floats2half2_rn(e[8]*inv, 0.0f);
            __half2 hxx = __floats2half2_rn(0.0f, 0.0f);
            uint2 u0, u1, u2;
            u0.x = *(unsigned int*)&h01; u0.y = *(unsigned int*)&h23;
            u1.x = *(unsigned int*)&h45; u1.y = *(unsigned int*)&h67;
            u2.x = *(unsigned int*)&h8x; u2.y = *(unsigned int*)&hxx;
            *(uint2*)(dst)     = u0;
            *(uint2*)(dst + 4) = u1;
            *(uint2*)(dst + 8) = u2;
        }
    }
}

// ============================================================================
// Kernel C (FUSED): aggregation + fold + output projection.
// Phase 1 = exact R8 agg (v window in smem, collapsed 5x5 stencil), but the
// fold tile stays in SMEM (written into the v-window buffer after a sync).
// Phase 2 = R8-gemm-style: out[d][q] = sum_c fold[c][q]*Wp[c][d] + bp[d],
// Wp streamed in 48-row smem chunks. Eliminates the 77MB Fold round-trip
// and the separate gemm-D launch. smem 111,360B -> still 2 blocks/SM.
// ============================================================================
#define AGG_SMEM_BYTES (96*145*8)                // 111360
#define FSTR 68                                  // fold row stride (16B-mult)

__global__ void __launch_bounds__(384, 2) aggproj_kernel(
    const float* __restrict__ V, const __half* __restrict__ Att,
    const float* __restrict__ Wp, const float* __restrict__ bp,
    float* __restrict__ Out)
{
    extern __shared__ char smraw[];
    unsigned long long* vsm2 = (unsigned long long*)smraw;      // [96][145]
    float* fsm = (float*)smraw;                                 // [192][68]
    float* wsm = (float*)(smraw + 192*FSTR*4);                  // [48][192]
    const int tid = threadIdx.x;
    const int blk = blockIdx.x;
    const int n   = blk / 49;
    const int tt  = blk - n*49;
    const int y0  = (tt / 7) * 8, x0 = (tt % 7) * 8;

    // ---- Phase 1a: load v window (96 channel pairs) ----
    for (int i = tid; i < 96*144; i += 384) {
        int cp = i / 144, pos = i - cp*144;
        int ly = pos / 12, lx = pos - ly*12;
        int gy = y0 - 2 + ly, gx = x0 - 2 + lx;
        float a = 0.0f, b = 0.0f;
        if (gy >= 0 && gy < HH && gx >= 0 && gx < WW) {
            const float* vb = &V[((size_t)(n*CC) + 2*cp)*HWP + gy*WW + gx];
            a = vb[0]; b = vb[HWP];
        }
        vsm2[cp*145 + pos] = pack2(a, b);
    }
    __syncthreads();

    // ---- Phase 1b: collapsed stencil + aggregation into registers ----
    unsigned long long facc[16];
    const int head = tid >> 6;          // 0..5
    const int q    = tid & 63;
    {
        const int qy = q >> 3, qx = q & 7;
        const int gy = y0 + qy, gx = x0 + qx;

        float W2[25];
        #pragma unroll
        for (int p = 0; p < 25; p++) W2[p] = 0.0f;
        const __half* hbase = Att + ((size_t)n*54 + head*9)*HWP*12;
        #pragma unroll
        for (int i = 0; i < 3; i++)
        #pragma unroll
        for (int j = 0; j < 3; j++) {
            int py = gy + 1 - i, px = gx + 1 - j;
            if (py >= 0 && py < HH && px >= 0 && px < WW) {
                const __half* ab = hbase + ((size_t)(i*3+j)*HWP + py*WW + px)*12;
                uint2 u0 = *(const uint2*)(ab);
                uint2 u1 = *(const uint2*)(ab + 4);
                unsigned int u2 = *(const unsigned int*)(ab + 8);
                __half2 h01 = *(__half2*)&u0.x, h23 = *(__half2*)&u0.y;
                __half2 h45 = *(__half2*)&u1.x, h67 = *(__half2*)&u1.y;
                __half2 h8x = *(__half2*)&u2;
                float2 f01 = __half22float2(h01);
                float2 f23 = __half22float2(h23);
                float2 f45 = __half22float2(h45);
                float2 f67 = __half22float2(h67);
                float  f8  = __low2float(h8x);
                float av[9] = {f01.x, f01.y, f23.x, f23.y,
                               f45.x, f45.y, f67.x, f67.y, f8};
                #pragma unroll
                for (int a = 0; a < 3; a++)
                #pragma unroll
                for (int b = 0; b < 3; b++)
                    W2[(a-i+2)*5 + (b-j+2)] += av[a*3+b];
            }
        }

        #pragma unroll
        for (int c16 = 0; c16 < 16; c16++) facc[c16] = 0ull;
        const unsigned long long* vbase = vsm2 + (head*16)*145 + qy*12 + qx;
        #pragma unroll
        for (int p = 0; p < 25; p++) {
            const int off = (p/5)*12 + (p%5);
            unsigned long long w2 = pack2(W2[p], W2[p]);
            #pragma unroll
            for (int c16 = 0; c16 < 16; c16++)
                FMA2(facc[c16], vbase[c16*145 + off], w2);
        }
    }
    __syncthreads();      // all vsm2 reads complete before buffer reuse

    // ---- write fold tile into smem (reusing the v-window buffer) ----
    #pragma unroll
    for (int c16 = 0; c16 < 16; c16++) {
        float xa, ya;
        unpack2(facc[c16], xa, ya);
        int c = head*32 + 2*c16;
        fsm[(c    )*FSTR + q] = xa;
        fsm[(c + 1)*FSTR + q] = ya;
    }

    // ---- Phase 2: out[d][q] = sum_c fold[c][q] * Wp[c][d] + bp[d] ----
    const int dg  = tid >> 4;       // 0..23 -> d [8dg, 8dg+8)
    const int pg2 = tid & 15;       // 0..15 -> q  [4pg2, 4pg2+4)

    unsigned long long acc2[8][2];
    #pragma unroll
    for (int di = 0; di < 8; di++) {
        float bb = bp[8*dg + di];
        unsigned long long b2 = pack2(bb, bb);
        acc2[di][0] = b2; acc2[di][1] = b2;
    }

    for (int kc = 0; kc < 4; kc++) {
        __syncthreads();   // (first iter: also publishes fsm writes)
        // wsm chunk: rows kc*48..+48 of Wp, all 192 cols = 2304 float4
        #pragma unroll
        for (int s = 0; s < 6; s++) {
            int idx = tid + s*384;
            int k = idx / 48, c4 = idx - k*48;
            *(float4*)&wsm[k*192 + c4*4] =
                *(const float4*)&Wp[(size_t)(kc*48 + k)*192 + c4*4];
        }
        __syncthreads();

        #pragma unroll 4
        for (int r = 0; r < 48; r++) {
            const int c = kc*48 + r;
            float4 wa = *(const float4*)&wsm[r*192 + 8*dg];
            float4 wb = *(const float4*)&wsm[r*192 + 8*dg + 4];
            ulonglong2 xv = *(const ulonglong2*)&fsm[c*FSTR + 4*pg2];
            unsigned long long xp0 = xv.x, xp1 = xv.y;
            unsigned long long w2[8];
            w2[0]=pack2(wa.x,wa.x); w2[1]=pack2(wa.y,wa.y);
            w2[2]=pack2(wa.z,wa.z); w2[3]=pack2(wa.w,wa.w);
            w2[4]=pack2(wb.x,wb.x); w2[5]=pack2(wb.y,wb.y);
            w2[6]=pack2(wb.z,wb.z); w2[7]=pack2(wb.w,wb.w);
            #pragma unroll
            for (int di = 0; di < 8; di++) {
                FMA2(acc2[di][0], xp0, w2[di]);
                FMA2(acc2[di][1], xp1, w2[di]);
            }
        }
    }

    // ---- epilogue: direct coalesced stores to Out ----
    {
        const int qy2 = pg2 >> 1, qx2 = (pg2 & 1) * 4;
        float* ob = Out + ((size_t)(n*CC) + 8*dg)*HWP + (y0 + qy2)*WW + x0 + qx2;
        #pragma unroll
        for (int di = 0; di < 8; di++) {
            ulonglong2 uv; uv.x = acc2[di][0]; uv.y = acc2[di][1];
            *(ulonglong2*)&ob[(size_t)di*HWP] = uv;
        }
    }
}

// ============================================================================
// Launch
// ============================================================================
extern "C" void kernel_launch(void* const* d_in, const int* in_sizes, int n_in,
                              void* d_out, int out_size)
{
    const float* x  = (const float*)d_in[0];
    const float* Wv = (const float*)d_in[1];
    const float* Wa = (const float*)d_in[2];
    const float* ba = (const float*)d_in[3];
    const float* Wp = (const float*)d_in[4];
    const float* bp = (const float*)d_in[5];
    float* out = (float*)d_out;

    float *vp, *wpad;
    __half* ap;
    cudaGetSymbolAddress((void**)&vp, g_v);
    cudaGetSymbolAddress((void**)&ap, g_att);
    cudaGetSymbolAddress((void**)&wpad, g_wpad);

    cudaFuncSetAttribute(att_kernel,     cudaFuncAttributeMaxDynamicSharedMemorySize, ATT_SMEM_BYTES);
    cudaFuncSetAttribute(aggproj_kernel, cudaFuncAttributeMaxDynamicSharedMemorySize, AGG_SMEM_BYTES);

    // pad Wa -> [192][648]
    pad_wa_kernel<<<(CC*KTP + 255)/256, 256>>>(Wa, wpad);
    // value projection: v = x @ Wv
    gemm192_kernel<<<392*2, 192>>>(x, Wv, nullptr, vp);
    // attention logits + fused softmax (fp16 plane-major output)
    att_kernel<<<NB*49, 864, ATT_SMEM_BYTES>>>(x, wpad, ba, ap);
    // FUSED: aggregation + fold + output projection -> d_out
    aggproj_kernel<<<NB*49, 384, AGG_SMEM_BYTES>>>(vp, ap, Wp, bp, out);
}

// round 14
// speedup vs baseline: 1.5187x; 1.5187x over previous
#include <cuda_runtime.h>
#include <cuda_fp16.h>
#include <cstdint>
#include <cstddef>

#define NB    16
#define CC    192
#define HH    56
#define WW    56
#define HWP   (HH*WW)          // 3136
#define NPIX  (NB*HWP)         // 50176
#define HEADS 6
#define CHN   32
#define KT    486              // 81 * 6
#define KTP   648              // padded: 54 groups * 12
#define SCALE 0.17677669529663689f   // 32^-0.5

// ---------------- scratch (device globals; no runtime allocation) -------------
__device__ float  g_v   [NB*CC*HWP];                 // value projection    (38.5 MB)
// att layout: [n][head][kout][pixel][12] in FP16 (65 MB, plane-major)
__device__ __half g_att [(size_t)NB*HEADS*9*HWP*12];
__device__ float  g_fold[NB*CC*HWP];                 // folded result       (38.5 MB)
__device__ float  g_wpad[CC*KTP];                    // padded Wa           (497 KB)

// ---------------- packed f32x2 helpers ---------------------------------------
#define FMA2(acc,a,b) asm("fma.rn.f32x2 %0, %1, %2, %0;" : "+l"(acc) : "l"(a), "l"(b))

__device__ __forceinline__ unsigned long long pack2(float x, float y) {
    unsigned long long r;
    asm("mov.b64 %0, {%1, %2};" : "=l"(r) : "r"(__float_as_uint(x)), "r"(__float_as_uint(y)));
    return r;
}
__device__ __forceinline__ void unpack2(unsigned long long v, float& x, float& y) {
    unsigned int lo, hi;
    asm("mov.b64 {%0, %1}, %2;" : "=r"(lo), "=r"(hi) : "l"(v));
    x = __uint_as_float(lo); y = __uint_as_float(hi);
}

// ---------------- cp.async helpers -------------------------------------------
__device__ __forceinline__ void cp_async16(void* smem_ptr, const void* gptr) {
    unsigned int saddr = (unsigned int)__cvta_generic_to_shared(smem_ptr);
    asm volatile("cp.async.cg.shared.global [%0], [%1], 16;"
                 :: "r"(saddr), "l"(gptr) : "memory");
}
#define CP_COMMIT() asm volatile("cp.async.commit_group;" ::: "memory")
#define CP_WAIT0()  asm volatile("cp.async.wait_group 0;" ::: "memory")

// ============================================================================
// Wa pre-pad: [192][486] -> [192][648], group g's 9 cols at 12g..12g+8, pad 0.
// ============================================================================
__global__ void pad_wa_kernel(const float* __restrict__ Wa, float* __restrict__ Wp)
{
    int i = blockIdx.x * 256 + threadIdx.x;
    if (i >= CC*KTP) return;
    int c = i / KTP, col = i - c*KTP;
    int g = col / 12, u = col - g*12;
    Wp[i] = (u < 9) ? Wa[c*KT + g*9 + u] : 0.0f;
}

// ============================================================================
// Kernel A/D: 192x192 pointwise GEMM. Exact R8 version.
// ============================================================================
__global__ void __launch_bounds__(192, 3) gemm192_kernel(
    const float* __restrict__ X, const float* __restrict__ Wm,
    const float* __restrict__ bias, float* __restrict__ Out)
{
    __shared__ float xs[48][128];
    __shared__ float ws[48][96];
    const int tid  = threadIdx.x;
    const int b    = blockIdx.x;
    const int pt   = b >> 1;
    const int dt   = b & 1;
    const int g0   = pt * 128;
    const int dbase= dt * 96;
    const int warp = tid >> 5, lane = tid & 31;
    const int wd   = warp % 3, wp = warp / 3;
    const int ld   = lane >> 3, lp = lane & 7;
    const int d0   = wd*32 + ld*8;
    const int p0   = wp*64 + lp*8;

    unsigned long long acc[8][4];
    #pragma unroll
    for (int di = 0; di < 8; di++) {
        float bb = bias ? bias[dbase + d0 + di] : 0.0f;
        unsigned long long b2 = pack2(bb, bb);
        #pragma unroll
        for (int pp = 0; pp < 4; pp++) acc[di][pp] = b2;
    }

    for (int kc = 0; kc < 4; kc++) {
        __syncthreads();
        #pragma unroll
        for (int s = 0; s < 8; s++) {
            int idx = tid + s*192;
            int k = idx >> 5, p4 = idx & 31;
            int g = g0 + p4*4;
            int n = g / HWP, hw = g - n*HWP;
            *(float4*)&xs[k][p4*4] =
                *(const float4*)&X[((size_t)(n*CC) + kc*48 + k)*HWP + hw];
        }
        #pragma unroll
        for (int s = 0; s < 6; s++) {
            int idx = tid + s*192;
            int k = idx / 24, c4 = idx - k*24;
            *(float4*)&ws[k][c4*4] =
                *(const float4*)&Wm[(size_t)(kc*48 + k)*192 + dbase + c4*4];
        }
        __syncthreads();

        #pragma unroll 4
        for (int r = 0; r < 48; r++) {
            float4 wa = *(const float4*)&ws[r][d0];
            float4 wb = *(const float4*)&ws[r][d0+4];
            ulonglong2 xv0 = *(const ulonglong2*)&xs[r][p0];
            ulonglong2 xv1 = *(const ulonglong2*)&xs[r][p0+4];
            unsigned long long xp[4] = {xv0.x, xv0.y, xv1.x, xv1.y};
            unsigned long long w2[8];
            w2[0]=pack2(wa.x,wa.x); w2[1]=pack2(wa.y,wa.y);
            w2[2]=pack2(wa.z,wa.z); w2[3]=pack2(wa.w,wa.w);
            w2[4]=pack2(wb.x,wb.x); w2[5]=pack2(wb.y,wb.y);
            w2[6]=pack2(wb.z,wb.z); w2[7]=pack2(wb.w,wb.w);
            #pragma unroll
            for (int di = 0; di < 8; di++)
                #pragma unroll
                for (int pp = 0; pp < 4; pp++)
                    FMA2(acc[di][pp], xp[pp], w2[di]);
        }
    }

    #pragma unroll
    for (int s = 0; s < 2; s++) {
        int g = g0 + p0 + s*4;
        int n = g / HWP, hw = g - n*HWP;
        #pragma unroll
        for (int di = 0; di < 8; di++) {
            ulonglong2 uv; uv.x = acc[di][2*s]; uv.y = acc[di][2*s+1];
            *(ulonglong2*)&Out[((size_t)(n*CC) + dbase + d0 + di)*HWP + hw] = uv;
        }
    }
}

// ============================================================================
// Kernel B: attention logits GEMM + fused register softmax.
// R8 compute, NEW: double-buffered smem with cp.async prefetch — the next
// K-chunk's x/Wa tiles stream into buffer B (async copy engine, no registers)
// while the FMA loop consumes buffer A. Fill latency fully hidden.
// smem = 2 x 91,136 = 182,272B (1 block/SM — occupancy unchanged; the
// overlap comes from cp.async, not co-residency).
// ============================================================================
#define ATT_BUF_FLOATS (32*64 + 32*KTP)          // 22784
#define ATT_SMEM_BYTES (2*ATT_BUF_FLOATS*4)      // 182272

__global__ void __launch_bounds__(864, 1) att_kernel(
    const float* __restrict__ X, const float* __restrict__ Wpad,
    const float* __restrict__ ba, __half* __restrict__ Att)
{
    extern __shared__ float sm[];
    const int tid = threadIdx.x;
    const int cg  = tid >> 4;       // 0..53  (= head*9 + kout)
    const int pg  = tid & 15;       // 0..15 -> px [4pg, 4pg+4)
    const int bb  = blockIdx.x;
    const int n   = bb / 49;
    const int hw0 = (bb - n*49) * 64;

    // async fill of one buffer for K-chunk kc
    auto fill = [&](int kc, int buf) {
        float* xsb = sm + buf*ATT_BUF_FLOATS;          // [32][64]
        float* wsb = xsb + 32*64;                      // [32][648]
        if (tid < 512) {
            int k = tid >> 4, p4 = tid & 15;
            cp_async16(&xsb[k*64 + p4*4],
                       &X[((size_t)(n*CC) + kc*32 + k)*HWP + hw0 + p4*4]);
        }
        #pragma unroll
        for (int s = 0; s < 6; s++) {
            int idx = tid + s*864;
            int k = idx / 162, c4 = idx - k*162;
            cp_async16(&wsb[k*KTP + c4*4],
                       &Wpad[(size_t)(kc*32 + k)*KTP + c4*4]);
        }
    };

    unsigned long long acc[9][2];
    #pragma unroll
    for (int u = 0; u < 9; u++) {
        float bv = ba[9*cg + u];
        unsigned long long b2 = pack2(bv, bv);
        acc[u][0] = b2; acc[u][1] = b2;
    }

    fill(0, 0); CP_COMMIT(); CP_WAIT0();
    __syncthreads();

    for (int kc = 0; kc < 6; kc++) {
        const int buf = kc & 1;
        if (kc < 5) { fill(kc + 1, buf ^ 1); CP_COMMIT(); }

        const float* xs = sm + buf*ATT_BUF_FLOATS;
        const float* ws = xs + 32*64;

        #pragma unroll 2
        for (int r = 0; r < 32; r++) {
            float4 q0 = *(const float4*)&ws[r*KTP + 12*cg];
            float4 q1 = *(const float4*)&ws[r*KTP + 12*cg + 4];
            float  q8 = ws[r*KTP + 12*cg + 8];
            ulonglong2 xv = *(const ulonglong2*)&xs[r*64 + 4*pg];
            unsigned long long xp0 = xv.x, xp1 = xv.y;
            float wv[9] = {q0.x,q0.y,q0.z,q0.w,q1.x,q1.y,q1.z,q1.w,q8};
            #pragma unroll
            for (int u = 0; u < 9; u++) {
                unsigned long long w2 = pack2(wv[u], wv[u]);
                FMA2(acc[u][0], xp0, w2);
                FMA2(acc[u][1], xp1, w2);
            }
        }

        if (kc < 5) CP_WAIT0();
        __syncthreads();
    }

    __half* planeBase = Att + ((size_t)n*54 + cg)*HWP*12;

    #pragma unroll
    for (int pp = 0; pp < 2; pp++) {
        float z0[9], z1[9];
        #pragma unroll
        for (int u = 0; u < 9; u++) unpack2(acc[u][pp], z0[u], z1[u]);
        #pragma unroll
        for (int half = 0; half < 2; half++) {
            float* z = half ? z1 : z0;
            float m = z[0];
            #pragma unroll
            for (int u = 1; u < 9; u++) m = fmaxf(m, z[u]);
            float e[9], s = 0.0f;
            #pragma unroll
            for (int u = 0; u < 9; u++) { e[u] = __expf((z[u]-m)*SCALE); s += e[u]; }
            float inv = 1.0f / s;
            int px = 4*pg + 2*pp + half;
            __half* dst = planeBase + (size_t)(hw0 + px)*12;
            __half2 h01 = __floats2half2_rn(e[0]*inv, e[1]*inv);
            __half2 h23 = __floats2half2_rn(e[2]*inv, e[3]*inv);
            __half2 h45 = __floats2half2_rn(e[4]*inv, e[5]*inv);
            __half2 h67 = __floats2half2_rn(e[6]*inv, e[7]*inv);
            __half2 h8x = __floats2half2_rn(e[8]*inv, 0.0f);
            __half2 hxx = __floats2half2_rn(0.0f, 0.0f);
            uint2 u0, u1, u2;
            u0.x = *(unsigned int*)&h01; u0.y = *(unsigned int*)&h23;
            u1.x = *(unsigned int*)&h45; u1.y = *(unsigned int*)&h67;
            u2.x = *(unsigned int*)&h8x; u2.y = *(unsigned int*)&hxx;
            *(uint2*)(dst)     = u0;
            *(uint2*)(dst + 4) = u1;
            *(uint2*)(dst + 8) = u2;
        }
    }
}

// ============================================================================
// Kernel C: aggregation + fold, 5x5 collapsed stencil. Exact R8 version.
// ============================================================================
#define AGG_SMEM_BYTES (96*145*8)                // 111360

__global__ void __launch_bounds__(384, 2) agg_kernel(
    const float* __restrict__ V, const __half* __restrict__ Att,
    float* __restrict__ Fold)
{
    extern __shared__ char smraw[];
    unsigned long long* vsm2 = (unsigned long long*)smraw;      // [96][145]
    const int tid = threadIdx.x;
    const int blk = blockIdx.x;
    const int n   = blk / 49;
    const int tt  = blk - n*49;
    const int y0  = (tt / 7) * 8, x0 = (tt % 7) * 8;

    for (int i = tid; i < 96*144; i += 384) {
        int cp = i / 144, pos = i - cp*144;
        int ly = pos / 12, lx = pos - ly*12;
        int gy = y0 - 2 + ly, gx = x0 - 2 + lx;
        float a = 0.0f, b = 0.0f;
        if (gy >= 0 && gy < HH && gx >= 0 && gx < WW) {
            const float* vb = &V[((size_t)(n*CC) + 2*cp)*HWP + gy*WW + gx];
            a = vb[0]; b = vb[HWP];
        }
        vsm2[cp*145 + pos] = pack2(a, b);
    }
    __syncthreads();

    {
        const int head = tid >> 6;          // 0..5
        const int q    = tid & 63;
        const int qy = q >> 3, qx = q & 7;
        const int gy = y0 + qy, gx = x0 + qx;

        float W2[25];
        #pragma unroll
        for (int p = 0; p < 25; p++) W2[p] = 0.0f;
        const __half* hbase = Att + ((size_t)n*54 + head*9)*HWP*12;
        #pragma unroll
        for (int i = 0; i < 3; i++)
        #pragma unroll
        for (int j = 0; j < 3; j++) {
            int py = gy + 1 - i, px = gx + 1 - j;
            if (py >= 0 && py < HH && px >= 0 && px < WW) {
                const __half* ab = hbase + ((size_t)(i*3+j)*HWP + py*WW + px)*12;
                uint2 u0 = *(const uint2*)(ab);
                uint2 u1 = *(const uint2*)(ab + 4);
                unsigned int u2 = *(const unsigned int*)(ab + 8);
                __half2 h01 = *(__half2*)&u0.x, h23 = *(__half2*)&u0.y;
                __half2 h45 = *(__half2*)&u1.x, h67 = *(__half2*)&u1.y;
                __half2 h8x = *(__half2*)&u2;
                float2 f01 = __half22float2(h01);
                float2 f23 = __half22float2(h23);
                float2 f45 = __half22float2(h45);
                float2 f67 = __half22float2(h67);
                float  f8  = __low2float(h8x);
                float av[9] = {f01.x, f01.y, f23.x, f23.y,
                               f45.x, f45.y, f67.x, f67.y, f8};
                #pragma unroll
                for (int a = 0; a < 3; a++)
                #pragma unroll
                for (int b = 0; b < 3; b++)
                    W2[(a-i+2)*5 + (b-j+2)] += av[a*3+b];
            }
        }

        unsigned long long acc[16];
        #pragma unroll
        for (int c16 = 0; c16 < 16; c16++) acc[c16] = 0ull;
        const unsigned long long* vbase = vsm2 + (head*16)*145 + qy*12 + qx;
        #pragma unroll
        for (int p = 0; p < 25; p++) {
            const int off = (p/5)*12 + (p%5);
            unsigned long long w2 = pack2(W2[p], W2[p]);
            #pragma unroll
            for (int c16 = 0; c16 < 16; c16++)
                FMA2(acc[c16], vbase[c16*145 + off], w2);
        }

        float* foutbase = Fold + ((size_t)(n*CC))*HWP + gy*WW + gx;
        #pragma unroll
        for (int c16 = 0; c16 < 16; c16++) {
            const int cp = head*16 + c16;
            float xa, ya;
            unpack2(acc[c16], xa, ya);
            foutbase[(size_t)(2*cp    )*HWP] = xa;
            foutbase[(size_t)(2*cp + 1)*HWP] = ya;
        }
    }
}

// ============================================================================
// Launch
// ============================================================================
extern "C" void kernel_launch(void* const* d_in, const int* in_sizes, int n_in,
                              void* d_out, int out_size)
{
    const float* x  = (const float*)d_in[0];
    const float* Wv = (const float*)d_in[1];
    const float* Wa = (const float*)d_in[2];
    const float* ba = (const float*)d_in[3];
    const float* Wp = (const float*)d_in[4];
    const float* bp = (const float*)d_in[5];
    float* out = (float*)d_out;

    float *vp, *fp, *wpad;
    __half* ap;
    cudaGetSymbolAddress((void**)&vp, g_v);
    cudaGetSymbolAddress((void**)&ap, g_att);
    cudaGetSymbolAddress((void**)&fp, g_fold);
    cudaGetSymbolAddress((void**)&wpad, g_wpad);

    cudaFuncSetAttribute(att_kernel, cudaFuncAttributeMaxDynamicSharedMemorySize, ATT_SMEM_BYTES);
    cudaFuncSetAttribute(agg_kernel, cudaFuncAttributeMaxDynamicSharedMemorySize, AGG_SMEM_BYTES);

    // pad Wa -> [192][648]
    pad_wa_kernel<<<(CC*KTP + 255)/256, 256>>>(Wa, wpad);
    // value projection: v = x @ Wv
    gemm192_kernel<<<392*2, 192>>>(x, Wv, nullptr, vp);
    // attention logits + fused softmax (cp.async double-buffered)
    att_kernel<<<NB*49, 864, ATT_SMEM_BYTES>>>(x, wpad, ba, ap);
    // aggregation + fold (collapsed 5x5 stencil, fp16 att gather)
    agg_kernel<<<NB*49, 384, AGG_SMEM_BYTES>>>(vp, ap, fp);
    // output projection: out = folded @ Wp + bp
    gemm192_kernel<<<392*2, 192>>>(fp, Wp, bp, out);
}